// round 14
// baseline (speedup 1.0000x reference)
#include <cuda_runtime.h>
#include <cuda_fp16.h>
#include <math_constants.h>
#include <cstdint>

#define DIMK   2048
#define NBLK   2000
#define NPAD   2048
#define NROWS  32768
#define T_PER_B 1024
#define NB_HALF 16

#define BM 128
#define BN 128
#define BKH 32               // k-halfs per stage
#define NITER (DIMK / BKH)   // 64
#define NSTG 5
#define NTH 256              // 8 warps, 64x32 warp tiles

#define ROW_STRIDE 80                    // padded row stride (conflict-free)
#define TILE_B (128 * ROW_STRIDE)        // 10240 B
#define B_REG_OFF (NSTG * TILE_B)        // 51200
#define EPIL_OFF_B (2 * NSTG * TILE_B)   // 102400
#define SMEM_BYTES (EPIL_OFF_B + 3712)   // 106112 -> 2 CTAs/SM (212KB)

#define N_ATT_CTAS 4096
#define N_DIV_CTAS 136

// ---------------- device scratch ----------------
__device__ __half       g_xh[(size_t)NROWS * DIMK];
__device__ __half       g_whn[(size_t)NPAD * DIMK];
__device__ __half       g_whr[(size_t)NPAD * DIMK];
__device__ unsigned int g_rowmax[NROWS];
__device__ float        g_s[NB_HALF * NBLK];
__device__ float        g_div;
__device__ float        g_bmin[32];
__device__ float        g_smaxv[NB_HALF];
__device__ float        g_sinvv[NB_HALF];

// ---------------- helpers ----------------
__device__ __forceinline__ unsigned int enc_f(float f) {
    unsigned int u = __float_as_uint(f);
    return (u & 0x80000000u) ? ~u : (u | 0x80000000u);
}
__device__ __forceinline__ float dec_f(unsigned int u) {
    unsigned int b = (u & 0x80000000u) ? (u ^ 0x80000000u) : ~u;
    return __uint_as_float(b);
}
__device__ __forceinline__ uint32_t smem_u32(const void* p) {
    uint32_t a;
    asm("{ .reg .u64 t; cvta.to.shared.u64 t, %1; cvt.u32.u64 %0, t; }" : "=r"(a) : "l"(p));
    return a;
}
__device__ __forceinline__ void cp16(uint32_t dst, const void* src) {
    asm volatile("cp.async.cg.shared.global [%0], [%1], 16;"
                 :: "r"(dst), "l"(src) : "memory");
}
#define CP_COMMIT() asm volatile("cp.async.commit_group;" ::: "memory")
#define CP_WAIT3()  asm volatile("cp.async.wait_group 3;" ::: "memory")
#define CP_WAIT0()  asm volatile("cp.async.wait_group 0;" ::: "memory")

__device__ __forceinline__ void ldsm_x4(uint32_t* r, uint32_t addr) {
    asm volatile("ldmatrix.sync.aligned.m8n8.x4.shared.b16 {%0,%1,%2,%3}, [%4];"
                 : "=r"(r[0]), "=r"(r[1]), "=r"(r[2]), "=r"(r[3]) : "r"(addr));
}
__device__ __forceinline__ void mma_f16(float* d, uint32_t a0, uint32_t a1,
                                        uint32_t a2, uint32_t a3,
                                        uint32_t b0, uint32_t b1) {
    asm volatile(
        "mma.sync.aligned.m16n8k16.row.col.f32.f16.f16.f32 "
        "{%0,%1,%2,%3}, {%4,%5,%6,%7}, {%8,%9}, {%0,%1,%2,%3};"
        : "+f"(d[0]), "+f"(d[1]), "+f"(d[2]), "+f"(d[3])
        : "r"(a0), "r"(a1), "r"(a2), "r"(a3), "r"(b0), "r"(b1));
}

__device__ __forceinline__ float blk_sum256(float v, float* sm) {
    int lane = threadIdx.x & 31, wid = threadIdx.x >> 5;
    #pragma unroll
    for (int o = 16; o; o >>= 1) v += __shfl_down_sync(0xffffffffu, v, o);
    if (lane == 0) sm[wid] = v;
    __syncthreads();
    float t = (threadIdx.x < 8) ? sm[threadIdx.x] : 0.0f;
    if (wid == 0) {
        #pragma unroll
        for (int o = 4; o; o >>= 1) t += __shfl_down_sync(0xffu, t, o);
        if (lane == 0) sm[0] = t;
    }
    __syncthreads();
    return sm[0];
}

// ---------------- merged normalize + convert (X rows then W rows) ----------------
__global__ void conv_kernel(const float* __restrict__ X, const float* __restrict__ W) {
    __shared__ float sm[8];
    int r = blockIdx.x, tid = threadIdx.x;
    if (r < NROWS) {
        if (tid == 0) g_rowmax[r] = 0u;
        if (r < 125) g_s[r * 256 + tid] = 0.0f;
        if (r == 0 && tid == 1) g_div = 0.0f;

        const float4* xp = (const float4*)(X + (size_t)r * DIMK);
        float4 v0 = xp[tid], v1 = xp[tid + 256];
        float ss = v0.x*v0.x + v0.y*v0.y + v0.z*v0.z + v0.w*v0.w
                 + v1.x*v1.x + v1.y*v1.y + v1.z*v1.z + v1.w*v1.w;
        ss = blk_sum256(ss, sm);
        float inv = 1.0f / fmaxf(sqrtf(ss), 1e-12f);
        __half2* out = (__half2*)(g_xh + (size_t)r * DIMK);
        out[2*tid + 0]     = __floats2half2_rn(v0.x * inv, v0.y * inv);
        out[2*tid + 1]     = __floats2half2_rn(v0.z * inv, v0.w * inv);
        out[2*(tid+256)]   = __floats2half2_rn(v1.x * inv, v1.y * inv);
        out[2*(tid+256)+1] = __floats2half2_rn(v1.z * inv, v1.w * inv);
    } else {
        int rw = r - NROWS;
        __half2* on  = (__half2*)(g_whn + (size_t)rw * DIMK);
        __half2* orr = (__half2*)(g_whr + (size_t)rw * DIMK);
        if (rw < NBLK) {
            const float4* wp = (const float4*)(W + (size_t)rw * DIMK);
            float4 v0 = wp[tid], v1 = wp[tid + 256];
            float ss = v0.x*v0.x + v0.y*v0.y + v0.z*v0.z + v0.w*v0.w
                     + v1.x*v1.x + v1.y*v1.y + v1.z*v1.z + v1.w*v1.w;
            ss = blk_sum256(ss, sm);
            float inv = 1.0f / fmaxf(sqrtf(ss), 1e-12f);
            on[2*tid]         = __floats2half2_rn(v0.x*inv, v0.y*inv);
            on[2*tid+1]       = __floats2half2_rn(v0.z*inv, v0.w*inv);
            on[2*(tid+256)]   = __floats2half2_rn(v1.x*inv, v1.y*inv);
            on[2*(tid+256)+1] = __floats2half2_rn(v1.z*inv, v1.w*inv);
            orr[2*tid]         = __floats2half2_rn(v0.x, v0.y);
            orr[2*tid+1]       = __floats2half2_rn(v0.z, v0.w);
            orr[2*(tid+256)]   = __floats2half2_rn(v1.x, v1.y);
            orr[2*(tid+256)+1] = __floats2half2_rn(v1.z, v1.w);
        } else {
            __half2 z = __floats2half2_rn(0.0f, 0.0f);
            on[2*tid] = z; on[2*tid+1] = z; on[2*(tid+256)] = z; on[2*(tid+256)+1] = z;
            orr[2*tid] = z; orr[2*tid+1] = z; orr[2*(tid+256)] = z; orr[2*(tid+256)+1] = z;
        }
    }
}

// ---------------- fp16 mma GEMM: 8 warps (2x4), 64x32 warp tiles ----------------
// 5-buffer pipeline, barrier per stage, loads 4 stages ahead, wait_group 3.
// Warp-staggered chunk order to spread LDSM bursts.
__global__ __launch_bounds__(NTH, 2)
void gemm_run(const int* __restrict__ mask) {
    extern __shared__ char smc[];
    float* rowfac_s = (float*)(smc + EPIL_OFF_B);  // [128]
    float* bias_s   = rowfac_s + 128;              // [128]
    float* csum_s   = bias_s + 128;                // [128]
    float* redm     = csum_s + 128;                // [128][4]

    const int tid  = threadIdx.x;
    const int lane = tid & 31, wid = tid >> 5;
    const int wm = wid >> 2, wn = wid & 3;
    const int g = lane >> 2, c = lane & 3;

    // ---- decode tile ----
    const int bid = blockIdx.x;
    const bool is_att = (bid < N_ATT_CTAS);
    int row0, col0;
    float dupw = 1.0f;
    const __half *A, *B;
    if (is_att) {
        col0 = (bid & 15) * BN;
        row0 = (bid >> 4) * BM;
        A = g_xh; B = g_whn;
    } else {
        int b = bid - N_ATT_CTAS;
        int ti = 0, rem = b;
        while (rem >= 16 - ti) { rem -= 16 - ti; ti++; }
        int tj = ti + rem;
        row0 = ti * BM;
        col0 = tj * BN;
        dupw = (ti == tj) ? 1.0f : 2.0f;
        A = g_whr; B = g_whr;
    }
    const bool fh = is_att && (row0 < NROWS / 2);

    if (is_att && tid < 128) {
        rowfac_s[tid] = (float)mask[row0 + tid];
        bias_s[tid] = (col0 + tid < NBLK) ? 0.0f : -CUDART_INF_F;
        csum_s[tid] = 0.0f;
    }

    // ---- cp.async setup ----
    const int q  = tid & 3;
    const int r0 = tid >> 2;
    const uint32_t sbase = smem_u32(smc);
    const uint32_t a_dst0 = sbase + (uint32_t)(r0 * ROW_STRIDE + q * 16);
    const uint32_t b_dst0 = a_dst0 + B_REG_OFF;
    const __half* a_run = A + (size_t)(row0 + r0) * DIMK + q * 8;
    const __half* b_run = B + (size_t)(col0 + r0) * DIMK + q * 8;

    // ---- fragment addresses ----
    const int mA = lane >> 3, r7 = lane & 7;
    const int gbA = mA >> 1, gbB = mA & 1;
    const uint32_t aFB = sbase + (uint32_t)((wm * 64 + r7 + ((mA & 1) << 3)) * ROW_STRIDE);
    const uint32_t bFB = sbase + B_REG_OFF + (uint32_t)((wn * 32 + r7 + ((mA >> 1) << 3)) * ROW_STRIDE);
    const uint32_t xA0 = (uint32_t)(gbA * 16), xA1 = xA0 + 32;
    const uint32_t xB0 = (uint32_t)(gbB * 16), xB1 = xB0 + 32;
    const bool oddw = (wid & 1) != 0;
    // staggered chunk order (both orders accumulate identically)
    const uint32_t cxa0 = oddw ? xA1 : xA0, cxb0 = oddw ? xB1 : xB0;
    const uint32_t cxa1 = oddw ? xA0 : xA1, cxb1 = oddw ? xB0 : xB1;

    // ---- accumulators ----
    float d[4][4][4];
    #pragma unroll
    for (int i = 0; i < 4; i++)
        #pragma unroll
        for (int j = 0; j < 4; j++)
            #pragma unroll
            for (int r = 0; r < 4; r++) d[i][j][r] = 0.0f;

    auto load_stage = [&](uint32_t bufoff) {
        cp16(a_dst0 + bufoff,                   a_run);
        cp16(a_dst0 + bufoff + 64 * ROW_STRIDE, a_run + (size_t)64 * DIMK);
        cp16(b_dst0 + bufoff,                   b_run);
        cp16(b_dst0 + bufoff + 64 * ROW_STRIDE, b_run + (size_t)64 * DIMK);
        a_run += BKH; b_run += BKH;
        CP_COMMIT();
    };

    auto compute_chunk = [&](uint32_t ab, uint32_t bb, uint32_t xa, uint32_t xb) {
        uint32_t bf[2][4];
        #pragma unroll
        for (int jp = 0; jp < 2; jp++)
            ldsm_x4(bf[jp], bb + jp * (16 * ROW_STRIDE) + xb);
        #pragma unroll
        for (int ib = 0; ib < 4; ib++) {
            uint32_t af[4];
            ldsm_x4(af, ab + ib * (16 * ROW_STRIDE) + xa);
            #pragma unroll
            for (int jp = 0; jp < 2; jp++) {
                mma_f16(d[ib][2*jp],   af[0], af[1], af[2], af[3], bf[jp][0], bf[jp][1]);
                mma_f16(d[ib][2*jp+1], af[0], af[1], af[2], af[3], bf[jp][2], bf[jp][3]);
            }
        }
    };

    // preload stages 0..3
    load_stage(0);
    load_stage(TILE_B);
    load_stage(2 * TILE_B);
    load_stage(3 * TILE_B);

    int bufc = 0, bufl = 4;
    #pragma unroll 1
    for (int s = 0; s < NITER; s++) {
        CP_WAIT3();
        __syncthreads();
        if (s < NITER - 4) load_stage((uint32_t)(bufl * TILE_B));
        else CP_COMMIT();   // keep group count consistent for WAIT3
        const uint32_t ab = aFB + bufc * TILE_B;
        const uint32_t bb = bFB + bufc * TILE_B;
        compute_chunk(ab, bb, cxa0, cxb0);
        compute_chunk(ab, bb, cxa1, cxb1);
        bufc = (bufc == NSTG - 1) ? 0 : bufc + 1;
        bufl = (bufl == NSTG - 1) ? 0 : bufl + 1;
    }
    CP_WAIT0();

    // ---------------- epilogue ----------------
    if (is_att) {
        #pragma unroll
        for (int i = 0; i < 4; i++) {
            float m0 = -CUDART_INF_F, m1 = -CUDART_INF_F;
            #pragma unroll
            for (int jn = 0; jn < 4; jn++) {
                int nb = wn * 32 + jn * 8 + 2 * c;
                float bz0 = bias_s[nb], bz1 = bias_s[nb + 1];
                m0 = fmaxf(m0, fmaxf(d[i][jn][0] + bz0, d[i][jn][1] + bz1));
                m1 = fmaxf(m1, fmaxf(d[i][jn][2] + bz0, d[i][jn][3] + bz1));
            }
            m0 = fmaxf(m0, __shfl_xor_sync(0xffffffffu, m0, 1));
            m0 = fmaxf(m0, __shfl_xor_sync(0xffffffffu, m0, 2));
            m1 = fmaxf(m1, __shfl_xor_sync(0xffffffffu, m1, 1));
            m1 = fmaxf(m1, __shfl_xor_sync(0xffffffffu, m1, 2));
            if (c == 0) {
                redm[(wm * 64 + i * 16 + g) * 4 + wn]     = m0;
                redm[(wm * 64 + i * 16 + g + 8) * 4 + wn] = m1;
            }
        }
        if (fh) {
            float cs[4][2];
            #pragma unroll
            for (int jn = 0; jn < 4; jn++) { cs[jn][0] = 0.0f; cs[jn][1] = 0.0f; }
            #pragma unroll
            for (int i = 0; i < 4; i++) {
                float rf0 = rowfac_s[wm * 64 + i * 16 + g];
                float rf1 = rowfac_s[wm * 64 + i * 16 + g + 8];
                #pragma unroll
                for (int jn = 0; jn < 4; jn++) {
                    cs[jn][0] += d[i][jn][0] * rf0 + d[i][jn][2] * rf1;
                    cs[jn][1] += d[i][jn][1] * rf0 + d[i][jn][3] * rf1;
                }
            }
            #pragma unroll
            for (int jn = 0; jn < 4; jn++) {
                #pragma unroll
                for (int u = 0; u < 2; u++) {
                    float s = cs[jn][u];
                    s += __shfl_xor_sync(0xffffffffu, s, 4);
                    s += __shfl_xor_sync(0xffffffffu, s, 8);
                    s += __shfl_xor_sync(0xffffffffu, s, 16);
                    if (lane < 4) atomicAdd(&csum_s[wn * 32 + jn * 8 + 2 * c + u], s);
                }
            }
        }
        __syncthreads();
        if (tid < 128) {
            float m = fmaxf(fmaxf(redm[tid * 4 + 0], redm[tid * 4 + 1]),
                            fmaxf(redm[tid * 4 + 2], redm[tid * 4 + 3]));
            atomicMax(&g_rowmax[row0 + tid], enc_f(m));
        }
        if (fh && tid < 128) {
            int n = col0 + tid;
            if (n < NBLK) {
                int b = row0 >> 10;
                atomicAdd(&g_s[b * NBLK + n], csum_s[tid]);
            }
        }
    } else {
        float acc = 0.0f;
        #pragma unroll
        for (int i = 0; i < 4; i++) {
            int m0 = row0 + wm * 64 + i * 16 + g;
            #pragma unroll
            for (int jn = 0; jn < 4; jn++) {
                int n0 = col0 + wn * 32 + jn * 8 + 2 * c;
                float e;
                e = d[i][jn][0] - ((m0 == n0     && m0 < NBLK) ? 1.0f : 0.0f); acc += e * e;
                e = d[i][jn][1] - ((m0 == n0 + 1 && m0 < NBLK) ? 1.0f : 0.0f); acc += e * e;
                e = d[i][jn][2] - ((m0 + 8 == n0     && m0 + 8 < NBLK) ? 1.0f : 0.0f); acc += e * e;
                e = d[i][jn][3] - ((m0 + 8 == n0 + 1 && m0 + 8 < NBLK) ? 1.0f : 0.0f); acc += e * e;
            }
        }
        acc *= dupw;
        #pragma unroll
        for (int o = 16; o; o >>= 1) acc += __shfl_xor_sync(0xffffffffu, acc, o);
        if (lane == 0) csum_s[wid] = acc;
        __syncthreads();
        if (tid == 0) {
            float t = 0.0f;
            #pragma unroll
            for (int w = 0; w < 8; w++) t += csum_s[w];
            atomicAdd(&g_div, t);
        }
    }
}

// ---------------- finalize stage 1: 48 blocks ----------------
__global__ void finalize1_kernel(const int* __restrict__ mask) {
    __shared__ float red[32];
    int bidx = blockIdx.x, tid = threadIdx.x;
    int lane = tid & 31, wid = tid >> 5;
    if (bidx < 32) {
        int b = bidx;
        float mn = CUDART_INF_F;
        for (int t = tid; t < T_PER_B; t += blockDim.x) {
            int gr = b * T_PER_B + t;
            if (mask[gr] > 0) mn = fminf(mn, dec_f(g_rowmax[gr]));
        }
        #pragma unroll
        for (int o = 16; o; o >>= 1) mn = fminf(mn, __shfl_down_sync(0xffffffffu, mn, o));
        if (lane == 0) red[wid] = mn;
        __syncthreads();
        if (wid == 0) {
            float v = (lane < (int)(blockDim.x >> 5)) ? red[lane] : CUDART_INF_F;
            #pragma unroll
            for (int o = 16; o; o >>= 1) v = fminf(v, __shfl_down_sync(0xffffffffu, v, o));
            if (lane == 0) g_bmin[b] = v;
        }
    } else {
        int b = bidx - 32;
        float mx = -CUDART_INF_F;
        for (int n = tid; n < NBLK; n += blockDim.x) mx = fmaxf(mx, g_s[b * NBLK + n]);
        #pragma unroll
        for (int o = 16; o; o >>= 1) mx = fmaxf(mx, __shfl_down_sync(0xffffffffu, mx, o));
        if (lane == 0) red[wid] = mx;
        __syncthreads();
        if (wid == 0) {
            float v = (lane < (int)(blockDim.x >> 5)) ? red[lane] : -CUDART_INF_F;
            #pragma unroll
            for (int o = 16; o; o >>= 1) v = fmaxf(v, __shfl_down_sync(0xffffffffu, v, o));
            if (lane == 0) red[0] = v;
        }
        __syncthreads();
        mx = red[0];
        float se = 0.0f;
        for (int n = tid; n < NBLK; n += blockDim.x) se += expf(g_s[b * NBLK + n] - mx);
        #pragma unroll
        for (int o = 16; o; o >>= 1) se += __shfl_down_sync(0xffffffffu, se, o);
        __syncthreads();
        if (lane == 0) red[wid] = se;
        __syncthreads();
        if (wid == 0) {
            float v = (lane < (int)(blockDim.x >> 5)) ? red[lane] : 0.0f;
            #pragma unroll
            for (int o = 16; o; o >>= 1) v += __shfl_down_sync(0xffffffffu, v, o);
            if (lane == 0) { g_smaxv[b] = mx; g_sinvv[b] = 1.0f / v; }
        }
    }
}

// ---------------- finalize stage 2: 1 block ----------------
__global__ void finalize2_kernel(float* __restrict__ out) {
    __shared__ float red[32];
    __shared__ float smax[NB_HALF], sinv[NB_HALF];
    int tid = threadIdx.x, lane = tid & 31, wid = tid >> 5;
    if (tid < NB_HALF) { smax[tid] = g_smaxv[tid]; sinv[tid] = g_sinvv[tid]; }
    __syncthreads();

    float usq = 0.0f;
    for (int n = tid; n < NBLK; n += blockDim.x) {
        float tmp = 0.0f;
        #pragma unroll
        for (int b = 0; b < NB_HALF; b++)
            tmp += expf(g_s[b * NBLK + n] - smax[b]) * sinv[b];
        tmp *= (1.0f / (float)NB_HALF);
        usq += tmp * tmp;
    }
    #pragma unroll
    for (int o = 16; o; o >>= 1) usq += __shfl_down_sync(0xffffffffu, usq, o);
    if (lane == 0) red[wid] = usq;
    __syncthreads();
    if (wid == 0) {
        float v = (lane < (int)(blockDim.x >> 5)) ? red[lane] : 0.0f;
        #pragma unroll
        for (int o = 16; o; o >>= 1) v += __shfl_down_sync(0xffffffffu, v, o);
        if (lane == 0) {
            float mean_min = 0.0f, mean_ab = 0.0f;
            for (int b = 0; b < NB_HALF; b++) { mean_min += g_bmin[b]; mean_ab += g_bmin[NB_HALF + b]; }
            mean_min *= (1.0f / (float)NB_HALF);
            mean_ab  *= (1.0f / (float)NB_HALF);
            out[0] = 0.2f * sqrtf(g_div);
            out[1] = 2.0f - mean_min + mean_ab;
            out[2] = 0.5f * sqrtf(v);
        }
    }
}

// ---------------- launch ----------------
extern "C" void kernel_launch(void* const* d_in, const int* in_sizes, int n_in,
                              void* d_out, int out_size) {
    const float* x = nullptr;
    const int*   mask = nullptr;
    const float* w = nullptr;
    for (int i = 0; i < n_in; i++) {
        if (in_sizes[i] == NROWS * DIMK)      x = (const float*)d_in[i];
        else if (in_sizes[i] == NROWS)        mask = (const int*)d_in[i];
        else if (in_sizes[i] == NBLK * DIMK)  w = (const float*)d_in[i];
    }
    float* out = (float*)d_out;

    cudaFuncSetAttribute(gemm_run, cudaFuncAttributeMaxDynamicSharedMemorySize, SMEM_BYTES);

    conv_kernel<<<NROWS + NPAD, 256>>>(x, w);
    gemm_run<<<N_ATT_CTAS + N_DIV_CTAS, NTH, SMEM_BYTES>>>(mask);
    finalize1_kernel<<<48, 256>>>(mask);
    finalize2_kernel<<<1, 1024>>>(out);
}

// round 15
// speedup vs baseline: 1.0842x; 1.0842x over previous
#include <cuda_runtime.h>
#include <cuda_fp16.h>
#include <math_constants.h>
#include <cstdint>

#define DIMK   2048
#define NBLK   2000
#define NPAD   2048
#define NROWS  32768
#define T_PER_B 1024
#define NB_HALF 16

#define BM 128
#define BN 128
#define BKH 32               // k-halfs per stage
#define NITER (DIMK / BKH)   // 64
#define NSTG 4
#define NTH 256              // 8 warps, 64x32 warp tiles

#define ROW_STRIDE 80                    // padded row stride (conflict-free)
#define TILE_B (128 * ROW_STRIDE)        // 10240 B
#define B_REG_OFF (NSTG * TILE_B)        // 40960
#define EPIL_OFF_B (2 * NSTG * TILE_B)   // 81920
#define SMEM_BYTES (EPIL_OFF_B + 3712)   // 85632 -> 2 CTAs/SM

#define N_ATT_CTAS 4096
#define N_DIV_CTAS 136

// ---------------- device scratch ----------------
__device__ __half       g_xh[(size_t)NROWS * DIMK];
__device__ __half       g_whn[(size_t)NPAD * DIMK];
__device__ __half       g_whr[(size_t)NPAD * DIMK];
__device__ unsigned int g_rowmax[NROWS];
__device__ float        g_s[NB_HALF * NBLK];
__device__ float        g_div;
__device__ float        g_bmin[32];
__device__ float        g_smaxv[NB_HALF];
__device__ float        g_sinvv[NB_HALF];

// ---------------- helpers ----------------
__device__ __forceinline__ unsigned int enc_f(float f) {
    unsigned int u = __float_as_uint(f);
    return (u & 0x80000000u) ? ~u : (u | 0x80000000u);
}
__device__ __forceinline__ float dec_f(unsigned int u) {
    unsigned int b = (u & 0x80000000u) ? (u ^ 0x80000000u) : ~u;
    return __uint_as_float(b);
}
__device__ __forceinline__ uint32_t smem_u32(const void* p) {
    uint32_t a;
    asm("{ .reg .u64 t; cvta.to.shared.u64 t, %1; cvt.u32.u64 %0, t; }" : "=r"(a) : "l"(p));
    return a;
}
__device__ __forceinline__ void cp16(uint32_t dst, const void* src) {
    asm volatile("cp.async.cg.shared.global [%0], [%1], 16;"
                 :: "r"(dst), "l"(src) : "memory");
}
#define CP_COMMIT() asm volatile("cp.async.commit_group;" ::: "memory")
#define CP_WAIT2()  asm volatile("cp.async.wait_group 2;" ::: "memory")
#define CP_WAIT0()  asm volatile("cp.async.wait_group 0;" ::: "memory")

__device__ __forceinline__ void ldsm_x4(uint32_t* r, uint32_t addr) {
    asm volatile("ldmatrix.sync.aligned.m8n8.x4.shared.b16 {%0,%1,%2,%3}, [%4];"
                 : "=r"(r[0]), "=r"(r[1]), "=r"(r[2]), "=r"(r[3]) : "r"(addr));
}
__device__ __forceinline__ void mma_f16(float* d, uint32_t a0, uint32_t a1,
                                        uint32_t a2, uint32_t a3,
                                        uint32_t b0, uint32_t b1) {
    asm volatile(
        "mma.sync.aligned.m16n8k16.row.col.f32.f16.f16.f32 "
        "{%0,%1,%2,%3}, {%4,%5,%6,%7}, {%8,%9}, {%0,%1,%2,%3};"
        : "+f"(d[0]), "+f"(d[1]), "+f"(d[2]), "+f"(d[3])
        : "r"(a0), "r"(a1), "r"(a2), "r"(a3), "r"(b0), "r"(b1));
}

__device__ __forceinline__ float blk_sum256(float v, float* sm) {
    int lane = threadIdx.x & 31, wid = threadIdx.x >> 5;
    #pragma unroll
    for (int o = 16; o; o >>= 1) v += __shfl_down_sync(0xffffffffu, v, o);
    if (lane == 0) sm[wid] = v;
    __syncthreads();
    float t = (threadIdx.x < 8) ? sm[threadIdx.x] : 0.0f;
    if (wid == 0) {
        #pragma unroll
        for (int o = 4; o; o >>= 1) t += __shfl_down_sync(0xffu, t, o);
        if (lane == 0) sm[0] = t;
    }
    __syncthreads();
    return sm[0];
}

// ---------------- merged normalize + convert (X rows then W rows) ----------------
__global__ void conv_kernel(const float* __restrict__ X, const float* __restrict__ W) {
    __shared__ float sm[8];
    int r = blockIdx.x, tid = threadIdx.x;
    if (r < NROWS) {
        if (tid == 0) g_rowmax[r] = 0u;
        if (r < 125) g_s[r * 256 + tid] = 0.0f;
        if (r == 0 && tid == 1) g_div = 0.0f;

        const float4* xp = (const float4*)(X + (size_t)r * DIMK);
        float4 v0 = xp[tid], v1 = xp[tid + 256];
        float ss = v0.x*v0.x + v0.y*v0.y + v0.z*v0.z + v0.w*v0.w
                 + v1.x*v1.x + v1.y*v1.y + v1.z*v1.z + v1.w*v1.w;
        ss = blk_sum256(ss, sm);
        float inv = 1.0f / fmaxf(sqrtf(ss), 1e-12f);
        __half2* out = (__half2*)(g_xh + (size_t)r * DIMK);
        out[2*tid + 0]     = __floats2half2_rn(v0.x * inv, v0.y * inv);
        out[2*tid + 1]     = __floats2half2_rn(v0.z * inv, v0.w * inv);
        out[2*(tid+256)]   = __floats2half2_rn(v1.x * inv, v1.y * inv);
        out[2*(tid+256)+1] = __floats2half2_rn(v1.z * inv, v1.w * inv);
    } else {
        int rw = r - NROWS;
        __half2* on  = (__half2*)(g_whn + (size_t)rw * DIMK);
        __half2* orr = (__half2*)(g_whr + (size_t)rw * DIMK);
        if (rw < NBLK) {
            const float4* wp = (const float4*)(W + (size_t)rw * DIMK);
            float4 v0 = wp[tid], v1 = wp[tid + 256];
            float ss = v0.x*v0.x + v0.y*v0.y + v0.z*v0.z + v0.w*v0.w
                     + v1.x*v1.x + v1.y*v1.y + v1.z*v1.z + v1.w*v1.w;
            ss = blk_sum256(ss, sm);
            float inv = 1.0f / fmaxf(sqrtf(ss), 1e-12f);
            on[2*tid]         = __floats2half2_rn(v0.x*inv, v0.y*inv);
            on[2*tid+1]       = __floats2half2_rn(v0.z*inv, v0.w*inv);
            on[2*(tid+256)]   = __floats2half2_rn(v1.x*inv, v1.y*inv);
            on[2*(tid+256)+1] = __floats2half2_rn(v1.z*inv, v1.w*inv);
            orr[2*tid]         = __floats2half2_rn(v0.x, v0.y);
            orr[2*tid+1]       = __floats2half2_rn(v0.z, v0.w);
            orr[2*(tid+256)]   = __floats2half2_rn(v1.x, v1.y);
            orr[2*(tid+256)+1] = __floats2half2_rn(v1.z, v1.w);
        } else {
            __half2 z = __floats2half2_rn(0.0f, 0.0f);
            on[2*tid] = z; on[2*tid+1] = z; on[2*(tid+256)] = z; on[2*(tid+256)+1] = z;
            orr[2*tid] = z; orr[2*tid+1] = z; orr[2*(tid+256)] = z; orr[2*(tid+256)+1] = z;
        }
    }
}

// ---------------- fp16 mma GEMM: 8 warps (2x4), 64x32 warp tiles ----------------
// 4-buffer pipeline, barrier per stage, loads 3 ahead (wait_group 2),
// prefetch issued BETWEEN the two compute chunks.
__global__ __launch_bounds__(NTH, 2)
void gemm_run(const int* __restrict__ mask) {
    extern __shared__ char smc[];
    float* rowfac_s = (float*)(smc + EPIL_OFF_B);  // [128]
    float* bias_s   = rowfac_s + 128;              // [128]
    float* csum_s   = bias_s + 128;                // [128]
    float* redm     = csum_s + 128;                // [128][4]

    const int tid  = threadIdx.x;
    const int lane = tid & 31, wid = tid >> 5;
    const int wm = wid >> 2, wn = wid & 3;
    const int g = lane >> 2, c = lane & 3;

    // ---- decode tile ----
    const int bid = blockIdx.x;
    const bool is_att = (bid < N_ATT_CTAS);
    int row0, col0;
    float dupw = 1.0f;
    const __half *A, *B;
    if (is_att) {
        col0 = (bid & 15) * BN;
        row0 = (bid >> 4) * BM;
        A = g_xh; B = g_whn;
    } else {
        int b = bid - N_ATT_CTAS;
        int ti = 0, rem = b;
        while (rem >= 16 - ti) { rem -= 16 - ti; ti++; }
        int tj = ti + rem;
        row0 = ti * BM;
        col0 = tj * BN;
        dupw = (ti == tj) ? 1.0f : 2.0f;
        A = g_whr; B = g_whr;
    }
    const bool fh = is_att && (row0 < NROWS / 2);

    if (is_att && tid < 128) {
        rowfac_s[tid] = (float)mask[row0 + tid];
        bias_s[tid] = (col0 + tid < NBLK) ? 0.0f : -CUDART_INF_F;
        csum_s[tid] = 0.0f;
    }

    // ---- cp.async setup ----
    const int q  = tid & 3;
    const int r0 = tid >> 2;
    const uint32_t sbase = smem_u32(smc);
    const uint32_t a_dst0 = sbase + (uint32_t)(r0 * ROW_STRIDE + q * 16);
    const uint32_t b_dst0 = a_dst0 + B_REG_OFF;
    const __half* a_run = A + (size_t)(row0 + r0) * DIMK + q * 8;
    const __half* b_run = B + (size_t)(col0 + r0) * DIMK + q * 8;

    // ---- fragment addresses ----
    const int mA = lane >> 3, r7 = lane & 7;
    const int gbA = mA >> 1, gbB = mA & 1;
    const uint32_t aFB = sbase + (uint32_t)((wm * 64 + r7 + ((mA & 1) << 3)) * ROW_STRIDE);
    const uint32_t bFB = sbase + B_REG_OFF + (uint32_t)((wn * 32 + r7 + ((mA >> 1) << 3)) * ROW_STRIDE);
    const uint32_t xA0 = (uint32_t)(gbA * 16), xA1 = xA0 + 32;
    const uint32_t xB0 = (uint32_t)(gbB * 16), xB1 = xB0 + 32;

    // ---- accumulators ----
    float d[4][4][4];
    #pragma unroll
    for (int i = 0; i < 4; i++)
        #pragma unroll
        for (int j = 0; j < 4; j++)
            #pragma unroll
            for (int r = 0; r < 4; r++) d[i][j][r] = 0.0f;

    auto load_stage = [&](uint32_t bufoff) {
        cp16(a_dst0 + bufoff,                   a_run);
        cp16(a_dst0 + bufoff + 64 * ROW_STRIDE, a_run + (size_t)64 * DIMK);
        cp16(b_dst0 + bufoff,                   b_run);
        cp16(b_dst0 + bufoff + 64 * ROW_STRIDE, b_run + (size_t)64 * DIMK);
        a_run += BKH; b_run += BKH;
        CP_COMMIT();
    };

    auto compute_chunk = [&](uint32_t ab, uint32_t bb, uint32_t xa, uint32_t xb) {
        uint32_t bf[2][4];
        #pragma unroll
        for (int jp = 0; jp < 2; jp++)
            ldsm_x4(bf[jp], bb + jp * (16 * ROW_STRIDE) + xb);
        #pragma unroll
        for (int ib = 0; ib < 4; ib++) {
            uint32_t af[4];
            ldsm_x4(af, ab + ib * (16 * ROW_STRIDE) + xa);
            #pragma unroll
            for (int jp = 0; jp < 2; jp++) {
                mma_f16(d[ib][2*jp],   af[0], af[1], af[2], af[3], bf[jp][0], bf[jp][1]);
                mma_f16(d[ib][2*jp+1], af[0], af[1], af[2], af[3], bf[jp][2], bf[jp][3]);
            }
        }
    };

    // preload stages 0,1,2
    load_stage(0);
    load_stage(TILE_B);
    load_stage(2 * TILE_B);

    int bufc = 0, bufl = 3;
    #pragma unroll 1
    for (int s = 0; s < NITER; s++) {
        CP_WAIT2();
        __syncthreads();
        const uint32_t ab = aFB + bufc * TILE_B;
        const uint32_t bb = bFB + bufc * TILE_B;
        compute_chunk(ab, bb, xA0, xB0);
        // prefetch between the two chunks: fragment LDSMs got LSU priority,
        // cp.async issue cost now hides under HMMA-busy window
        if (s < NITER - 3) load_stage((uint32_t)(bufl * TILE_B));
        else CP_COMMIT();
        compute_chunk(ab, bb, xA1, xB1);
        bufc = (bufc == NSTG - 1) ? 0 : bufc + 1;
        bufl = (bufl == NSTG - 1) ? 0 : bufl + 1;
    }
    CP_WAIT0();

    // ---------------- epilogue ----------------
    if (is_att) {
        #pragma unroll
        for (int i = 0; i < 4; i++) {
            float m0 = -CUDART_INF_F, m1 = -CUDART_INF_F;
            #pragma unroll
            for (int jn = 0; jn < 4; jn++) {
                int nb = wn * 32 + jn * 8 + 2 * c;
                float bz0 = bias_s[nb], bz1 = bias_s[nb + 1];
                m0 = fmaxf(m0, fmaxf(d[i][jn][0] + bz0, d[i][jn][1] + bz1));
                m1 = fmaxf(m1, fmaxf(d[i][jn][2] + bz0, d[i][jn][3] + bz1));
            }
            m0 = fmaxf(m0, __shfl_xor_sync(0xffffffffu, m0, 1));
            m0 = fmaxf(m0, __shfl_xor_sync(0xffffffffu, m0, 2));
            m1 = fmaxf(m1, __shfl_xor_sync(0xffffffffu, m1, 1));
            m1 = fmaxf(m1, __shfl_xor_sync(0xffffffffu, m1, 2));
            if (c == 0) {
                redm[(wm * 64 + i * 16 + g) * 4 + wn]     = m0;
                redm[(wm * 64 + i * 16 + g + 8) * 4 + wn] = m1;
            }
        }
        if (fh) {
            float cs[4][2];
            #pragma unroll
            for (int jn = 0; jn < 4; jn++) { cs[jn][0] = 0.0f; cs[jn][1] = 0.0f; }
            #pragma unroll
            for (int i = 0; i < 4; i++) {
                float rf0 = rowfac_s[wm * 64 + i * 16 + g];
                float rf1 = rowfac_s[wm * 64 + i * 16 + g + 8];
                #pragma unroll
                for (int jn = 0; jn < 4; jn++) {
                    cs[jn][0] += d[i][jn][0] * rf0 + d[i][jn][2] * rf1;
                    cs[jn][1] += d[i][jn][1] * rf0 + d[i][jn][3] * rf1;
                }
            }
            #pragma unroll
            for (int jn = 0; jn < 4; jn++) {
                #pragma unroll
                for (int u = 0; u < 2; u++) {
                    float s = cs[jn][u];
                    s += __shfl_xor_sync(0xffffffffu, s, 4);
                    s += __shfl_xor_sync(0xffffffffu, s, 8);
                    s += __shfl_xor_sync(0xffffffffu, s, 16);
                    if (lane < 4) atomicAdd(&csum_s[wn * 32 + jn * 8 + 2 * c + u], s);
                }
            }
        }
        __syncthreads();
        if (tid < 128) {
            float m = fmaxf(fmaxf(redm[tid * 4 + 0], redm[tid * 4 + 1]),
                            fmaxf(redm[tid * 4 + 2], redm[tid * 4 + 3]));
            atomicMax(&g_rowmax[row0 + tid], enc_f(m));
        }
        if (fh && tid < 128) {
            int n = col0 + tid;
            if (n < NBLK) {
                int b = row0 >> 10;
                atomicAdd(&g_s[b * NBLK + n], csum_s[tid]);
            }
        }
    } else {
        float acc = 0.0f;
        #pragma unroll
        for (int i = 0; i < 4; i++) {
            int m0 = row0 + wm * 64 + i * 16 + g;
            #pragma unroll
            for (int jn = 0; jn < 4; jn++) {
                int n0 = col0 + wn * 32 + jn * 8 + 2 * c;
                float e;
                e = d[i][jn][0] - ((m0 == n0     && m0 < NBLK) ? 1.0f : 0.0f); acc += e * e;
                e = d[i][jn][1] - ((m0 == n0 + 1 && m0 < NBLK) ? 1.0f : 0.0f); acc += e * e;
                e = d[i][jn][2] - ((m0 + 8 == n0     && m0 + 8 < NBLK) ? 1.0f : 0.0f); acc += e * e;
                e = d[i][jn][3] - ((m0 + 8 == n0 + 1 && m0 + 8 < NBLK) ? 1.0f : 0.0f); acc += e * e;
            }
        }
        acc *= dupw;
        #pragma unroll
        for (int o = 16; o; o >>= 1) acc += __shfl_xor_sync(0xffffffffu, acc, o);
        if (lane == 0) csum_s[wid] = acc;
        __syncthreads();
        if (tid == 0) {
            float t = 0.0f;
            #pragma unroll
            for (int w = 0; w < 8; w++) t += csum_s[w];
            atomicAdd(&g_div, t);
        }
    }
}

// ---------------- finalize stage 1: 48 blocks ----------------
__global__ void finalize1_kernel(const int* __restrict__ mask) {
    __shared__ float red[32];
    int bidx = blockIdx.x, tid = threadIdx.x;
    int lane = tid & 31, wid = tid >> 5;
    if (bidx < 32) {
        int b = bidx;
        float mn = CUDART_INF_F;
        for (int t = tid; t < T_PER_B; t += blockDim.x) {
            int gr = b * T_PER_B + t;
            if (mask[gr] > 0) mn = fminf(mn, dec_f(g_rowmax[gr]));
        }
        #pragma unroll
        for (int o = 16; o; o >>= 1) mn = fminf(mn, __shfl_down_sync(0xffffffffu, mn, o));
        if (lane == 0) red[wid] = mn;
        __syncthreads();
        if (wid == 0) {
            float v = (lane < (int)(blockDim.x >> 5)) ? red[lane] : CUDART_INF_F;
            #pragma unroll
            for (int o = 16; o; o >>= 1) v = fminf(v, __shfl_down_sync(0xffffffffu, v, o));
            if (lane == 0) g_bmin[b] = v;
        }
    } else {
        int b = bidx - 32;
        float mx = -CUDART_INF_F;
        for (int n = tid; n < NBLK; n += blockDim.x) mx = fmaxf(mx, g_s[b * NBLK + n]);
        #pragma unroll
        for (int o = 16; o; o >>= 1) mx = fmaxf(mx, __shfl_down_sync(0xffffffffu, mx, o));
        if (lane == 0) red[wid] = mx;
        __syncthreads();
        if (wid == 0) {
            float v = (lane < (int)(blockDim.x >> 5)) ? red[lane] : -CUDART_INF_F;
            #pragma unroll
            for (int o = 16; o; o >>= 1) v = fmaxf(v, __shfl_down_sync(0xffffffffu, v, o));
            if (lane == 0) red[0] = v;
        }
        __syncthreads();
        mx = red[0];
        float se = 0.0f;
        for (int n = tid; n < NBLK; n += blockDim.x) se += expf(g_s[b * NBLK + n] - mx);
        #pragma unroll
        for (int o = 16; o; o >>= 1) se += __shfl_down_sync(0xffffffffu, se, o);
        __syncthreads();
        if (lane == 0) red[wid] = se;
        __syncthreads();
        if (wid == 0) {
            float v = (lane < (int)(blockDim.x >> 5)) ? red[lane] : 0.0f;
            #pragma unroll
            for (int o = 16; o; o >>= 1) v += __shfl_down_sync(0xffffffffu, v, o);
            if (lane == 0) { g_smaxv[b] = mx; g_sinvv[b] = 1.0f / v; }
        }
    }
}

// ---------------- finalize stage 2: 1 block ----------------
__global__ void finalize2_kernel(float* __restrict__ out) {
    __shared__ float red[32];
    __shared__ float smax[NB_HALF], sinv[NB_HALF];
    int tid = threadIdx.x, lane = tid & 31, wid = tid >> 5;
    if (tid < NB_HALF) { smax[tid] = g_smaxv[tid]; sinv[tid] = g_sinvv[tid]; }
    __syncthreads();

    float usq = 0.0f;
    for (int n = tid; n < NBLK; n += blockDim.x) {
        float tmp = 0.0f;
        #pragma unroll
        for (int b = 0; b < NB_HALF; b++)
            tmp += expf(g_s[b * NBLK + n] - smax[b]) * sinv[b];
        tmp *= (1.0f / (float)NB_HALF);
        usq += tmp * tmp;
    }
    #pragma unroll
    for (int o = 16; o; o >>= 1) usq += __shfl_down_sync(0xffffffffu, usq, o);
    if (lane == 0) red[wid] = usq;
    __syncthreads();
    if (wid == 0) {
        float v = (lane < (int)(blockDim.x >> 5)) ? red[lane] : 0.0f;
        #pragma unroll
        for (int o = 16; o; o >>= 1) v += __shfl_down_sync(0xffffffffu, v, o);
        if (lane == 0) {
            float mean_min = 0.0f, mean_ab = 0.0f;
            for (int b = 0; b < NB_HALF; b++) { mean_min += g_bmin[b]; mean_ab += g_bmin[NB_HALF + b]; }
            mean_min *= (1.0f / (float)NB_HALF);
            mean_ab  *= (1.0f / (float)NB_HALF);
            out[0] = 0.2f * sqrtf(g_div);
            out[1] = 2.0f - mean_min + mean_ab;
            out[2] = 0.5f * sqrtf(v);
        }
    }
}

// ---------------- launch ----------------
extern "C" void kernel_launch(void* const* d_in, const int* in_sizes, int n_in,
                              void* d_out, int out_size) {
    const float* x = nullptr;
    const int*   mask = nullptr;
    const float* w = nullptr;
    for (int i = 0; i < n_in; i++) {
        if (in_sizes[i] == NROWS * DIMK)      x = (const float*)d_in[i];
        else if (in_sizes[i] == NROWS)        mask = (const int*)d_in[i];
        else if (in_sizes[i] == NBLK * DIMK)  w = (const float*)d_in[i];
    }
    float* out = (float*)d_out;

    cudaFuncSetAttribute(gemm_run, cudaFuncAttributeMaxDynamicSharedMemorySize, SMEM_BYTES);

    conv_kernel<<<NROWS + NPAD, 256>>>(x, w);
    gemm_run<<<N_ATT_CTAS + N_DIV_CTAS, NTH, SMEM_BYTES>>>(mask);
    finalize1_kernel<<<48, 256>>>(mask);
    finalize2_kernel<<<1, 1024>>>(out);
}

// round 16
// speedup vs baseline: 1.1671x; 1.0764x over previous
#include <cuda_runtime.h>
#include <cuda_fp16.h>
#include <math_constants.h>
#include <cstdint>

#define DIMK   2048
#define NBLK   2000
#define NPAD   2048
#define NROWS  32768
#define T_PER_B 1024
#define NB_HALF 16

#define BM 128
#define BN 128
#define BKH 64               // k-halfs per stage (128B data rows)
#define NITER (DIMK / BKH)   // 32
#define NSTG 3
#define NTH 256              // 8 warps, 64x32 warp tiles

#define ROW_STRIDE 144                   // padded row stride in bytes (conflict-free)
#define TILE_B (128 * ROW_STRIDE)        // 18432 B
#define B_REG_OFF (NSTG * TILE_B)        // 55296
#define EPIL_OFF_B (2 * NSTG * TILE_B)   // 110592
#define SMEM_BYTES (EPIL_OFF_B + 3712)   // 114304 -> 2 CTAs/SM (228.6KB)

#define N_ATT_CTAS 4096
#define N_DIV_CTAS 136

// ---------------- device scratch ----------------
__device__ __half       g_xh[(size_t)NROWS * DIMK];
__device__ __half       g_whn[(size_t)NPAD * DIMK];
__device__ __half       g_whr[(size_t)NPAD * DIMK];
__device__ unsigned int g_rowmax[NROWS];
__device__ float        g_s[NB_HALF * NBLK];
__device__ float        g_div;
__device__ float        g_bmin[32];
__device__ float        g_smaxv[NB_HALF];
__device__ float        g_sinvv[NB_HALF];

// ---------------- helpers ----------------
__device__ __forceinline__ unsigned int enc_f(float f) {
    unsigned int u = __float_as_uint(f);
    return (u & 0x80000000u) ? ~u : (u | 0x80000000u);
}
__device__ __forceinline__ float dec_f(unsigned int u) {
    unsigned int b = (u & 0x80000000u) ? (u ^ 0x80000000u) : ~u;
    return __uint_as_float(b);
}
__device__ __forceinline__ uint32_t smem_u32(const void* p) {
    uint32_t a;
    asm("{ .reg .u64 t; cvta.to.shared.u64 t, %1; cvt.u32.u64 %0, t; }" : "=r"(a) : "l"(p));
    return a;
}
__device__ __forceinline__ void cp16(uint32_t dst, const void* src) {
    asm volatile("cp.async.cg.shared.global [%0], [%1], 16;"
                 :: "r"(dst), "l"(src) : "memory");
}
#define CP_COMMIT() asm volatile("cp.async.commit_group;" ::: "memory")
#define CP_WAIT1()  asm volatile("cp.async.wait_group 1;" ::: "memory")
#define CP_WAIT0()  asm volatile("cp.async.wait_group 0;" ::: "memory")

__device__ __forceinline__ void ldsm_x4(uint32_t* r, uint32_t addr) {
    asm volatile("ldmatrix.sync.aligned.m8n8.x4.shared.b16 {%0,%1,%2,%3}, [%4];"
                 : "=r"(r[0]), "=r"(r[1]), "=r"(r[2]), "=r"(r[3]) : "r"(addr));
}
__device__ __forceinline__ void mma_f16(float* d, uint32_t a0, uint32_t a1,
                                        uint32_t a2, uint32_t a3,
                                        uint32_t b0, uint32_t b1) {
    asm volatile(
        "mma.sync.aligned.m16n8k16.row.col.f32.f16.f16.f32 "
        "{%0,%1,%2,%3}, {%4,%5,%6,%7}, {%8,%9}, {%0,%1,%2,%3};"
        : "+f"(d[0]), "+f"(d[1]), "+f"(d[2]), "+f"(d[3])
        : "r"(a0), "r"(a1), "r"(a2), "r"(a3), "r"(b0), "r"(b1));
}

__device__ __forceinline__ float blk_sum256(float v, float* sm) {
    int lane = threadIdx.x & 31, wid = threadIdx.x >> 5;
    #pragma unroll
    for (int o = 16; o; o >>= 1) v += __shfl_down_sync(0xffffffffu, v, o);
    if (lane == 0) sm[wid] = v;
    __syncthreads();
    float t = (threadIdx.x < 8) ? sm[threadIdx.x] : 0.0f;
    if (wid == 0) {
        #pragma unroll
        for (int o = 4; o; o >>= 1) t += __shfl_down_sync(0xffu, t, o);
        if (lane == 0) sm[0] = t;
    }
    __syncthreads();
    return sm[0];
}

// ---------------- merged normalize + convert (X rows then W rows) ----------------
__global__ void conv_kernel(const float* __restrict__ X, const float* __restrict__ W) {
    __shared__ float sm[8];
    int r = blockIdx.x, tid = threadIdx.x;
    if (r < NROWS) {
        if (tid == 0) g_rowmax[r] = 0u;
        if (r < 125) g_s[r * 256 + tid] = 0.0f;
        if (r == 0 && tid == 1) g_div = 0.0f;

        const float4* xp = (const float4*)(X + (size_t)r * DIMK);
        float4 v0 = xp[tid], v1 = xp[tid + 256];
        float ss = v0.x*v0.x + v0.y*v0.y + v0.z*v0.z + v0.w*v0.w
                 + v1.x*v1.x + v1.y*v1.y + v1.z*v1.z + v1.w*v1.w;
        ss = blk_sum256(ss, sm);
        float inv = 1.0f / fmaxf(sqrtf(ss), 1e-12f);
        __half2* out = (__half2*)(g_xh + (size_t)r * DIMK);
        out[2*tid + 0]     = __floats2half2_rn(v0.x * inv, v0.y * inv);
        out[2*tid + 1]     = __floats2half2_rn(v0.z * inv, v0.w * inv);
        out[2*(tid+256)]   = __floats2half2_rn(v1.x * inv, v1.y * inv);
        out[2*(tid+256)+1] = __floats2half2_rn(v1.z * inv, v1.w * inv);
    } else {
        int rw = r - NROWS;
        __half2* on  = (__half2*)(g_whn + (size_t)rw * DIMK);
        __half2* orr = (__half2*)(g_whr + (size_t)rw * DIMK);
        if (rw < NBLK) {
            const float4* wp = (const float4*)(W + (size_t)rw * DIMK);
            float4 v0 = wp[tid], v1 = wp[tid + 256];
            float ss = v0.x*v0.x + v0.y*v0.y + v0.z*v0.z + v0.w*v0.w
                     + v1.x*v1.x + v1.y*v1.y + v1.z*v1.z + v1.w*v1.w;
            ss = blk_sum256(ss, sm);
            float inv = 1.0f / fmaxf(sqrtf(ss), 1e-12f);
            on[2*tid]         = __floats2half2_rn(v0.x*inv, v0.y*inv);
            on[2*tid+1]       = __floats2half2_rn(v0.z*inv, v0.w*inv);
            on[2*(tid+256)]   = __floats2half2_rn(v1.x*inv, v1.y*inv);
            on[2*(tid+256)+1] = __floats2half2_rn(v1.z*inv, v1.w*inv);
            orr[2*tid]         = __floats2half2_rn(v0.x, v0.y);
            orr[2*tid+1]       = __floats2half2_rn(v0.z, v0.w);
            orr[2*(tid+256)]   = __floats2half2_rn(v1.x, v1.y);
            orr[2*(tid+256)+1] = __floats2half2_rn(v1.z, v1.w);
        } else {
            __half2 z = __floats2half2_rn(0.0f, 0.0f);
            on[2*tid] = z; on[2*tid+1] = z; on[2*(tid+256)] = z; on[2*(tid+256)+1] = z;
            orr[2*tid] = z; orr[2*tid+1] = z; orr[2*(tid+256)] = z; orr[2*(tid+256)+1] = z;
        }
    }
}

// ---------------- fp16 mma GEMM: 8 warps (2x4), 64x32 warp tiles, BKH=64 ----------------
// 3-buffer pipeline, barrier per stage (32 stages), loads 2 ahead (wait_group 1),
// prefetch issued after chunk 0 of 4.
__global__ __launch_bounds__(NTH, 2)
void gemm_run(const int* __restrict__ mask) {
    extern __shared__ char smc[];
    float* rowfac_s = (float*)(smc + EPIL_OFF_B);  // [128]
    float* bias_s   = rowfac_s + 128;              // [128]
    float* csum_s   = bias_s + 128;                // [128]
    float* redm     = csum_s + 128;                // [128][4]

    const int tid  = threadIdx.x;
    const int lane = tid & 31, wid = tid >> 5;
    const int wm = wid >> 2, wn = wid & 3;
    const int g = lane >> 2, c = lane & 3;

    // ---- decode tile ----
    const int bid = blockIdx.x;
    const bool is_att = (bid < N_ATT_CTAS);
    int row0, col0;
    float dupw = 1.0f;
    const __half *A, *B;
    if (is_att) {
        col0 = (bid & 15) * BN;
        row0 = (bid >> 4) * BM;
        A = g_xh; B = g_whn;
    } else {
        int b = bid - N_ATT_CTAS;
        int ti = 0, rem = b;
        while (rem >= 16 - ti) { rem -= 16 - ti; ti++; }
        int tj = ti + rem;
        row0 = ti * BM;
        col0 = tj * BN;
        dupw = (ti == tj) ? 1.0f : 2.0f;
        A = g_whr; B = g_whr;
    }
    const bool fh = is_att && (row0 < NROWS / 2);

    if (is_att && tid < 128) {
        rowfac_s[tid] = (float)mask[row0 + tid];
        bias_s[tid] = (col0 + tid < NBLK) ? 0.0f : -CUDART_INF_F;
        csum_s[tid] = 0.0f;
    }

    // ---- cp.async setup: 8 granules/row, 32 rows per pass, 4 passes ----
    const int q  = tid & 7;            // granule in row
    const int r0 = tid >> 3;           // 0..31
    const uint32_t sbase = smem_u32(smc);
    const uint32_t a_dst0 = sbase + (uint32_t)(r0 * ROW_STRIDE + q * 16);
    const uint32_t b_dst0 = a_dst0 + B_REG_OFF;
    const __half* a_run = A + (size_t)(row0 + r0) * DIMK + q * 8;
    const __half* b_run = B + (size_t)(col0 + r0) * DIMK + q * 8;

    // ---- fragment addresses ----
    const int mA = lane >> 3, r7 = lane & 7;
    const int gbA = mA >> 1, gbB = mA & 1;
    const uint32_t aFB = sbase + (uint32_t)((wm * 64 + r7 + ((mA & 1) << 3)) * ROW_STRIDE);
    const uint32_t bFB = sbase + B_REG_OFF + (uint32_t)((wn * 32 + r7 + ((mA >> 1) << 3)) * ROW_STRIDE);
    uint32_t xA[4], xB[4];
    #pragma unroll
    for (int ch = 0; ch < 4; ch++) {
        xA[ch] = (uint32_t)((2 * ch + gbA) * 16);
        xB[ch] = (uint32_t)((2 * ch + gbB) * 16);
    }

    // ---- accumulators ----
    float d[4][4][4];
    #pragma unroll
    for (int i = 0; i < 4; i++)
        #pragma unroll
        for (int j = 0; j < 4; j++)
            #pragma unroll
            for (int r = 0; r < 4; r++) d[i][j][r] = 0.0f;

    auto load_stage = [&](uint32_t bufoff) {
        #pragma unroll
        for (int i = 0; i < 4; i++) {
            cp16(a_dst0 + bufoff + i * (32 * ROW_STRIDE), a_run + (size_t)(32 * i) * DIMK);
            cp16(b_dst0 + bufoff + i * (32 * ROW_STRIDE), b_run + (size_t)(32 * i) * DIMK);
        }
        a_run += BKH; b_run += BKH;
        CP_COMMIT();
    };

    auto compute_chunk = [&](uint32_t ab, uint32_t bb, uint32_t xa, uint32_t xb) {
        uint32_t bf[2][4];
        #pragma unroll
        for (int jp = 0; jp < 2; jp++)
            ldsm_x4(bf[jp], bb + jp * (16 * ROW_STRIDE) + xb);
        #pragma unroll
        for (int ib = 0; ib < 4; ib++) {
            uint32_t af[4];
            ldsm_x4(af, ab + ib * (16 * ROW_STRIDE) + xa);
            #pragma unroll
            for (int jp = 0; jp < 2; jp++) {
                mma_f16(d[ib][2*jp],   af[0], af[1], af[2], af[3], bf[jp][0], bf[jp][1]);
                mma_f16(d[ib][2*jp+1], af[0], af[1], af[2], af[3], bf[jp][2], bf[jp][3]);
            }
        }
    };

    // preload stages 0,1
    load_stage(0);
    load_stage(TILE_B);

    int bufc = 0, bufl = 2;
    #pragma unroll 1
    for (int s = 0; s < NITER; s++) {
        CP_WAIT1();
        __syncthreads();
        const uint32_t ab = aFB + bufc * TILE_B;
        const uint32_t bb = bFB + bufc * TILE_B;
        compute_chunk(ab, bb, xA[0], xB[0]);
        if (s < NITER - 2) load_stage((uint32_t)(bufl * TILE_B));
        else CP_COMMIT();
        compute_chunk(ab, bb, xA[1], xB[1]);
        compute_chunk(ab, bb, xA[2], xB[2]);
        compute_chunk(ab, bb, xA[3], xB[3]);
        bufc = (bufc == NSTG - 1) ? 0 : bufc + 1;
        bufl = (bufl == NSTG - 1) ? 0 : bufl + 1;
    }
    CP_WAIT0();

    // ---------------- epilogue ----------------
    if (is_att) {
        #pragma unroll
        for (int i = 0; i < 4; i++) {
            float m0 = -CUDART_INF_F, m1 = -CUDART_INF_F;
            #pragma unroll
            for (int jn = 0; jn < 4; jn++) {
                int nb = wn * 32 + jn * 8 + 2 * c;
                float bz0 = bias_s[nb], bz1 = bias_s[nb + 1];
                m0 = fmaxf(m0, fmaxf(d[i][jn][0] + bz0, d[i][jn][1] + bz1));
                m1 = fmaxf(m1, fmaxf(d[i][jn][2] + bz0, d[i][jn][3] + bz1));
            }
            m0 = fmaxf(m0, __shfl_xor_sync(0xffffffffu, m0, 1));
            m0 = fmaxf(m0, __shfl_xor_sync(0xffffffffu, m0, 2));
            m1 = fmaxf(m1, __shfl_xor_sync(0xffffffffu, m1, 1));
            m1 = fmaxf(m1, __shfl_xor_sync(0xffffffffu, m1, 2));
            if (c == 0) {
                redm[(wm * 64 + i * 16 + g) * 4 + wn]     = m0;
                redm[(wm * 64 + i * 16 + g + 8) * 4 + wn] = m1;
            }
        }
        if (fh) {
            float cs[4][2];
            #pragma unroll
            for (int jn = 0; jn < 4; jn++) { cs[jn][0] = 0.0f; cs[jn][1] = 0.0f; }
            #pragma unroll
            for (int i = 0; i < 4; i++) {
                float rf0 = rowfac_s[wm * 64 + i * 16 + g];
                float rf1 = rowfac_s[wm * 64 + i * 16 + g + 8];
                #pragma unroll
                for (int jn = 0; jn < 4; jn++) {
                    cs[jn][0] += d[i][jn][0] * rf0 + d[i][jn][2] * rf1;
                    cs[jn][1] += d[i][jn][1] * rf0 + d[i][jn][3] * rf1;
                }
            }
            #pragma unroll
            for (int jn = 0; jn < 4; jn++) {
                #pragma unroll
                for (int u = 0; u < 2; u++) {
                    float s = cs[jn][u];
                    s += __shfl_xor_sync(0xffffffffu, s, 4);
                    s += __shfl_xor_sync(0xffffffffu, s, 8);
                    s += __shfl_xor_sync(0xffffffffu, s, 16);
                    if (lane < 4) atomicAdd(&csum_s[wn * 32 + jn * 8 + 2 * c + u], s);
                }
            }
        }
        __syncthreads();
        if (tid < 128) {
            float m = fmaxf(fmaxf(redm[tid * 4 + 0], redm[tid * 4 + 1]),
                            fmaxf(redm[tid * 4 + 2], redm[tid * 4 + 3]));
            atomicMax(&g_rowmax[row0 + tid], enc_f(m));
        }
        if (fh && tid < 128) {
            int n = col0 + tid;
            if (n < NBLK) {
                int b = row0 >> 10;
                atomicAdd(&g_s[b * NBLK + n], csum_s[tid]);
            }
        }
    } else {
        float acc = 0.0f;
        #pragma unroll
        for (int i = 0; i < 4; i++) {
            int m0 = row0 + wm * 64 + i * 16 + g;
            #pragma unroll
            for (int jn = 0; jn < 4; jn++) {
                int n0 = col0 + wn * 32 + jn * 8 + 2 * c;
                float e;
                e = d[i][jn][0] - ((m0 == n0     && m0 < NBLK) ? 1.0f : 0.0f); acc += e * e;
                e = d[i][jn][1] - ((m0 == n0 + 1 && m0 < NBLK) ? 1.0f : 0.0f); acc += e * e;
                e = d[i][jn][2] - ((m0 + 8 == n0     && m0 + 8 < NBLK) ? 1.0f : 0.0f); acc += e * e;
                e = d[i][jn][3] - ((m0 + 8 == n0 + 1 && m0 + 8 < NBLK) ? 1.0f : 0.0f); acc += e * e;
            }
        }
        acc *= dupw;
        #pragma unroll
        for (int o = 16; o; o >>= 1) acc += __shfl_xor_sync(0xffffffffu, acc, o);
        if (lane == 0) csum_s[wid] = acc;
        __syncthreads();
        if (tid == 0) {
            float t = 0.0f;
            #pragma unroll
            for (int w = 0; w < 8; w++) t += csum_s[w];
            atomicAdd(&g_div, t);
        }
    }
}

// ---------------- finalize stage 1: 48 blocks ----------------
__global__ void finalize1_kernel(const int* __restrict__ mask) {
    __shared__ float red[32];
    int bidx = blockIdx.x, tid = threadIdx.x;
    int lane = tid & 31, wid = tid >> 5;
    if (bidx < 32) {
        int b = bidx;
        float mn = CUDART_INF_F;
        for (int t = tid; t < T_PER_B; t += blockDim.x) {
            int gr = b * T_PER_B + t;
            if (mask[gr] > 0) mn = fminf(mn, dec_f(g_rowmax[gr]));
        }
        #pragma unroll
        for (int o = 16; o; o >>= 1) mn = fminf(mn, __shfl_down_sync(0xffffffffu, mn, o));
        if (lane == 0) red[wid] = mn;
        __syncthreads();
        if (wid == 0) {
            float v = (lane < (int)(blockDim.x >> 5)) ? red[lane] : CUDART_INF_F;
            #pragma unroll
            for (int o = 16; o; o >>= 1) v = fminf(v, __shfl_down_sync(0xffffffffu, v, o));
            if (lane == 0) g_bmin[b] = v;
        }
    } else {
        int b = bidx - 32;
        float mx = -CUDART_INF_F;
        for (int n = tid; n < NBLK; n += blockDim.x) mx = fmaxf(mx, g_s[b * NBLK + n]);
        #pragma unroll
        for (int o = 16; o; o >>= 1) mx = fmaxf(mx, __shfl_down_sync(0xffffffffu, mx, o));
        if (lane == 0) red[wid] = mx;
        __syncthreads();
        if (wid == 0) {
            float v = (lane < (int)(blockDim.x >> 5)) ? red[lane] : -CUDART_INF_F;
            #pragma unroll
            for (int o = 16; o; o >>= 1) v = fmaxf(v, __shfl_down_sync(0xffffffffu, v, o));
            if (lane == 0) red[0] = v;
        }
        __syncthreads();
        mx = red[0];
        float se = 0.0f;
        for (int n = tid; n < NBLK; n += blockDim.x) se += expf(g_s[b * NBLK + n] - mx);
        #pragma unroll
        for (int o = 16; o; o >>= 1) se += __shfl_down_sync(0xffffffffu, se, o);
        __syncthreads();
        if (lane == 0) red[wid] = se;
        __syncthreads();
        if (wid == 0) {
            float v = (lane < (int)(blockDim.x >> 5)) ? red[lane] : 0.0f;
            #pragma unroll
            for (int o = 16; o; o >>= 1) v += __shfl_down_sync(0xffffffffu, v, o);
            if (lane == 0) { g_smaxv[b] = mx; g_sinvv[b] = 1.0f / v; }
        }
    }
}

// ---------------- finalize stage 2: 1 block ----------------
__global__ void finalize2_kernel(float* __restrict__ out) {
    __shared__ float red[32];
    __shared__ float smax[NB_HALF], sinv[NB_HALF];
    int tid = threadIdx.x, lane = tid & 31, wid = tid >> 5;
    if (tid < NB_HALF) { smax[tid] = g_smaxv[tid]; sinv[tid] = g_sinvv[tid]; }
    __syncthreads();

    float usq = 0.0f;
    for (int n = tid; n < NBLK; n += blockDim.x) {
        float tmp = 0.0f;
        #pragma unroll
        for (int b = 0; b < NB_HALF; b++)
            tmp += expf(g_s[b * NBLK + n] - smax[b]) * sinv[b];
        tmp *= (1.0f / (float)NB_HALF);
        usq += tmp * tmp;
    }
    #pragma unroll
    for (int o = 16; o; o >>= 1) usq += __shfl_down_sync(0xffffffffu, usq, o);
    if (lane == 0) red[wid] = usq;
    __syncthreads();
    if (wid == 0) {
        float v = (lane < (int)(blockDim.x >> 5)) ? red[lane] : 0.0f;
        #pragma unroll
        for (int o = 16; o; o >>= 1) v += __shfl_down_sync(0xffffffffu, v, o);
        if (lane == 0) {
            float mean_min = 0.0f, mean_ab = 0.0f;
            for (int b = 0; b < NB_HALF; b++) { mean_min += g_bmin[b]; mean_ab += g_bmin[NB_HALF + b]; }
            mean_min *= (1.0f / (float)NB_HALF);
            mean_ab  *= (1.0f / (float)NB_HALF);
            out[0] = 0.2f * sqrtf(g_div);
            out[1] = 2.0f - mean_min + mean_ab;
            out[2] = 0.5f * sqrtf(v);
        }
    }
}

// ---------------- launch ----------------
extern "C" void kernel_launch(void* const* d_in, const int* in_sizes, int n_in,
                              void* d_out, int out_size) {
    const float* x = nullptr;
    const int*   mask = nullptr;
    const float* w = nullptr;
    for (int i = 0; i < n_in; i++) {
        if (in_sizes[i] == NROWS * DIMK)      x = (const float*)d_in[i];
        else if (in_sizes[i] == NROWS)        mask = (const int*)d_in[i];
        else if (in_sizes[i] == NBLK * DIMK)  w = (const float*)d_in[i];
    }
    float* out = (float*)d_out;

    cudaFuncSetAttribute(gemm_run, cudaFuncAttributeMaxDynamicSharedMemorySize, SMEM_BYTES);

    conv_kernel<<<NROWS + NPAD, 256>>>(x, w);
    gemm_run<<<N_ATT_CTAS + N_DIV_CTAS, NTH, SMEM_BYTES>>>(mask);
    finalize1_kernel<<<48, 256>>>(mask);
    finalize2_kernel<<<1, 1024>>>(out);
}

// round 17
// speedup vs baseline: 1.3525x; 1.1589x over previous
#include <cuda_runtime.h>
#include <cuda_fp16.h>
#include <math_constants.h>
#include <cstdint>

#define DIMK   2048
#define NBLK   2000
#define NPAD   2048
#define NROWS  32768
#define T_PER_B 1024
#define NB_HALF 16

#define BM 128
#define BN 128
#define BKH 64               // k-halfs per stage (128B data rows)
#define NITER (DIMK / BKH)   // 32
#define NSTG 3
#define NTH 256              // 8 warps, 64x32 warp tiles

#define ROW_B 128                        // dense 128B rows, XOR granule swizzle
#define TILE_B (128 * ROW_B)             // 16384 B
#define B_REG_OFF (NSTG * TILE_B)        // 49152
#define EPIL_OFF_B (2 * NSTG * TILE_B)   // 98304
#define SMEM_BYTES (EPIL_OFF_B + 3712)   // 102016 -> 2 CTAs/SM (204KB)

#define N_ATT_CTAS 4096
#define N_DIV_CTAS 136

// ---------------- device scratch ----------------
__device__ __half       g_xh[(size_t)NROWS * DIMK];
__device__ __half       g_whn[(size_t)NPAD * DIMK];
__device__ __half       g_whr[(size_t)NPAD * DIMK];
__device__ unsigned int g_rowmax[NROWS];
__device__ float        g_s[NB_HALF * NBLK];
__device__ float        g_div;
__device__ float        g_bmin[32];
__device__ float        g_smaxv[NB_HALF];
__device__ float        g_sinvv[NB_HALF];

// ---------------- helpers ----------------
__device__ __forceinline__ unsigned int enc_f(float f) {
    unsigned int u = __float_as_uint(f);
    return (u & 0x80000000u) ? ~u : (u | 0x80000000u);
}
__device__ __forceinline__ float dec_f(unsigned int u) {
    unsigned int b = (u & 0x80000000u) ? (u ^ 0x80000000u) : ~u;
    return __uint_as_float(b);
}
__device__ __forceinline__ uint32_t smem_u32(const void* p) {
    uint32_t a;
    asm("{ .reg .u64 t; cvta.to.shared.u64 t, %1; cvt.u32.u64 %0, t; }" : "=r"(a) : "l"(p));
    return a;
}
__device__ __forceinline__ void cp16(uint32_t dst, const void* src) {
    asm volatile("cp.async.cg.shared.global [%0], [%1], 16;"
                 :: "r"(dst), "l"(src) : "memory");
}
#define CP_COMMIT() asm volatile("cp.async.commit_group;" ::: "memory")
#define CP_WAIT1()  asm volatile("cp.async.wait_group 1;" ::: "memory")
#define CP_WAIT0()  asm volatile("cp.async.wait_group 0;" ::: "memory")

__device__ __forceinline__ void ldsm_x4(uint32_t* r, uint32_t addr) {
    asm volatile("ldmatrix.sync.aligned.m8n8.x4.shared.b16 {%0,%1,%2,%3}, [%4];"
                 : "=r"(r[0]), "=r"(r[1]), "=r"(r[2]), "=r"(r[3]) : "r"(addr));
}
__device__ __forceinline__ void mma_f16(float* d, uint32_t a0, uint32_t a1,
                                        uint32_t a2, uint32_t a3,
                                        uint32_t b0, uint32_t b1) {
    asm volatile(
        "mma.sync.aligned.m16n8k16.row.col.f32.f16.f16.f32 "
        "{%0,%1,%2,%3}, {%4,%5,%6,%7}, {%8,%9}, {%0,%1,%2,%3};"
        : "+f"(d[0]), "+f"(d[1]), "+f"(d[2]), "+f"(d[3])
        : "r"(a0), "r"(a1), "r"(a2), "r"(a3), "r"(b0), "r"(b1));
}

__device__ __forceinline__ float blk_sum256(float v, float* sm) {
    int lane = threadIdx.x & 31, wid = threadIdx.x >> 5;
    #pragma unroll
    for (int o = 16; o; o >>= 1) v += __shfl_down_sync(0xffffffffu, v, o);
    if (lane == 0) sm[wid] = v;
    __syncthreads();
    float t = (threadIdx.x < 8) ? sm[threadIdx.x] : 0.0f;
    if (wid == 0) {
        #pragma unroll
        for (int o = 4; o; o >>= 1) t += __shfl_down_sync(0xffu, t, o);
        if (lane == 0) sm[0] = t;
    }
    __syncthreads();
    return sm[0];
}

// ---------------- merged normalize + convert (X rows then W rows) ----------------
__global__ void conv_kernel(const float* __restrict__ X, const float* __restrict__ W) {
    __shared__ float sm[8];
    int r = blockIdx.x, tid = threadIdx.x;
    if (r < NROWS) {
        if (tid == 0) g_rowmax[r] = 0u;
        if (r < 125) g_s[r * 256 + tid] = 0.0f;
        if (r == 0 && tid == 1) g_div = 0.0f;

        const float4* xp = (const float4*)(X + (size_t)r * DIMK);
        float4 v0 = xp[tid], v1 = xp[tid + 256];
        float ss = v0.x*v0.x + v0.y*v0.y + v0.z*v0.z + v0.w*v0.w
                 + v1.x*v1.x + v1.y*v1.y + v1.z*v1.z + v1.w*v1.w;
        ss = blk_sum256(ss, sm);
        float inv = 1.0f / fmaxf(sqrtf(ss), 1e-12f);
        __half2* out = (__half2*)(g_xh + (size_t)r * DIMK);
        out[2*tid + 0]     = __floats2half2_rn(v0.x * inv, v0.y * inv);
        out[2*tid + 1]     = __floats2half2_rn(v0.z * inv, v0.w * inv);
        out[2*(tid+256)]   = __floats2half2_rn(v1.x * inv, v1.y * inv);
        out[2*(tid+256)+1] = __floats2half2_rn(v1.z * inv, v1.w * inv);
    } else {
        int rw = r - NROWS;
        __half2* on  = (__half2*)(g_whn + (size_t)rw * DIMK);
        __half2* orr = (__half2*)(g_whr + (size_t)rw * DIMK);
        if (rw < NBLK) {
            const float4* wp = (const float4*)(W + (size_t)rw * DIMK);
            float4 v0 = wp[tid], v1 = wp[tid + 256];
            float ss = v0.x*v0.x + v0.y*v0.y + v0.z*v0.z + v0.w*v0.w
                     + v1.x*v1.x + v1.y*v1.y + v1.z*v1.z + v1.w*v1.w;
            ss = blk_sum256(ss, sm);
            float inv = 1.0f / fmaxf(sqrtf(ss), 1e-12f);
            on[2*tid]         = __floats2half2_rn(v0.x*inv, v0.y*inv);
            on[2*tid+1]       = __floats2half2_rn(v0.z*inv, v0.w*inv);
            on[2*(tid+256)]   = __floats2half2_rn(v1.x*inv, v1.y*inv);
            on[2*(tid+256)+1] = __floats2half2_rn(v1.z*inv, v1.w*inv);
            orr[2*tid]         = __floats2half2_rn(v0.x, v0.y);
            orr[2*tid+1]       = __floats2half2_rn(v0.z, v0.w);
            orr[2*(tid+256)]   = __floats2half2_rn(v1.x, v1.y);
            orr[2*(tid+256)+1] = __floats2half2_rn(v1.z, v1.w);
        } else {
            __half2 z = __floats2half2_rn(0.0f, 0.0f);
            on[2*tid] = z; on[2*tid+1] = z; on[2*(tid+256)] = z; on[2*(tid+256)+1] = z;
            orr[2*tid] = z; orr[2*tid+1] = z; orr[2*(tid+256)] = z; orr[2*(tid+256)+1] = z;
        }
    }
}

// ---------------- fp16 mma GEMM: 8 warps (2x4), 64x32 warp tiles, BKH=64 ----------------
// 3-buffer pipeline, barrier per stage (32 stages), loads 2 ahead (wait_group 1),
// prefetch after chunk 0 of 4. Dense 128B rows, granule swizzle q ^ (row&7).
__global__ __launch_bounds__(NTH, 2)
void gemm_run(const int* __restrict__ mask) {
    extern __shared__ char smc[];
    float* rowfac_s = (float*)(smc + EPIL_OFF_B);  // [128]
    float* bias_s   = rowfac_s + 128;              // [128]
    float* csum_s   = bias_s + 128;                // [128]
    float* redm     = csum_s + 128;                // [128][4]

    const int tid  = threadIdx.x;
    const int lane = tid & 31, wid = tid >> 5;
    const int wm = wid >> 2, wn = wid & 3;
    const int g = lane >> 2, c = lane & 3;

    // ---- decode tile ----
    const int bid = blockIdx.x;
    const bool is_att = (bid < N_ATT_CTAS);
    int row0, col0;
    float dupw = 1.0f;
    const __half *A, *B;
    if (is_att) {
        col0 = (bid & 15) * BN;
        row0 = (bid >> 4) * BM;
        A = g_xh; B = g_whn;
    } else {
        int b = bid - N_ATT_CTAS;
        int ti = 0, rem = b;
        while (rem >= 16 - ti) { rem -= 16 - ti; ti++; }
        int tj = ti + rem;
        row0 = ti * BM;
        col0 = tj * BN;
        dupw = (ti == tj) ? 1.0f : 2.0f;
        A = g_whr; B = g_whr;
    }
    const bool fh = is_att && (row0 < NROWS / 2);

    if (is_att && tid < 128) {
        rowfac_s[tid] = (float)mask[row0 + tid];
        bias_s[tid] = (col0 + tid < NBLK) ? 0.0f : -CUDART_INF_F;
        csum_s[tid] = 0.0f;
    }

    // ---- cp.async setup: 8 granules/row, 32 rows per pass, 4 passes ----
    const int q  = tid & 7;            // granule in row
    const int r0 = tid >> 3;           // 0..31
    const uint32_t sbase = smem_u32(smc);
    const uint32_t a_dst0 = sbase + (uint32_t)(r0 * ROW_B + ((q ^ (r0 & 7)) << 4));
    const uint32_t b_dst0 = a_dst0 + B_REG_OFF;
    const __half* a_run = A + (size_t)(row0 + r0) * DIMK + q * 8;
    const __half* b_run = B + (size_t)(col0 + r0) * DIMK + q * 8;

    // ---- fragment addresses (all fragment row offsets are multiples of 8,
    //      so row&7 == r7 and the XOR folds into a per-thread constant) ----
    const int mA = lane >> 3, r7 = lane & 7;
    const int gbA = mA >> 1, gbB = mA & 1;
    const uint32_t aFB = sbase + (uint32_t)((wm * 64 + r7 + ((mA & 1) << 3)) * ROW_B);
    const uint32_t bFB = sbase + B_REG_OFF + (uint32_t)((wn * 32 + r7 + ((mA >> 1) << 3)) * ROW_B);
    uint32_t xA[4], xB[4];
    #pragma unroll
    for (int ch = 0; ch < 4; ch++) {
        xA[ch] = (uint32_t)(((2 * ch + gbA) ^ r7) << 4);
        xB[ch] = (uint32_t)(((2 * ch + gbB) ^ r7) << 4);
    }

    // ---- accumulators ----
    float d[4][4][4];
    #pragma unroll
    for (int i = 0; i < 4; i++)
        #pragma unroll
        for (int j = 0; j < 4; j++)
            #pragma unroll
            for (int r = 0; r < 4; r++) d[i][j][r] = 0.0f;

    auto load_stage = [&](uint32_t bufoff) {
        #pragma unroll
        for (int i = 0; i < 4; i++) {
            cp16(a_dst0 + bufoff + i * (32 * ROW_B), a_run + (size_t)(32 * i) * DIMK);
            cp16(b_dst0 + bufoff + i * (32 * ROW_B), b_run + (size_t)(32 * i) * DIMK);
        }
        a_run += BKH; b_run += BKH;
        CP_COMMIT();
    };

    auto compute_chunk = [&](uint32_t ab, uint32_t bb, uint32_t xa, uint32_t xb) {
        uint32_t bf[2][4];
        #pragma unroll
        for (int jp = 0; jp < 2; jp++)
            ldsm_x4(bf[jp], bb + jp * (16 * ROW_B) + xb);
        #pragma unroll
        for (int ib = 0; ib < 4; ib++) {
            uint32_t af[4];
            ldsm_x4(af, ab + ib * (16 * ROW_B) + xa);
            #pragma unroll
            for (int jp = 0; jp < 2; jp++) {
                mma_f16(d[ib][2*jp],   af[0], af[1], af[2], af[3], bf[jp][0], bf[jp][1]);
                mma_f16(d[ib][2*jp+1], af[0], af[1], af[2], af[3], bf[jp][2], bf[jp][3]);
            }
        }
    };

    // preload stages 0,1
    load_stage(0);
    load_stage(TILE_B);

    int bufc = 0, bufl = 2;
    #pragma unroll 1
    for (int s = 0; s < NITER; s++) {
        CP_WAIT1();
        __syncthreads();
        const uint32_t ab = aFB + bufc * TILE_B;
        const uint32_t bb = bFB + bufc * TILE_B;
        compute_chunk(ab, bb, xA[0], xB[0]);
        if (s < NITER - 2) load_stage((uint32_t)(bufl * TILE_B));
        else CP_COMMIT();
        compute_chunk(ab, bb, xA[1], xB[1]);
        compute_chunk(ab, bb, xA[2], xB[2]);
        compute_chunk(ab, bb, xA[3], xB[3]);
        bufc = (bufc == NSTG - 1) ? 0 : bufc + 1;
        bufl = (bufl == NSTG - 1) ? 0 : bufl + 1;
    }
    CP_WAIT0();

    // ---------------- epilogue ----------------
    if (is_att) {
        #pragma unroll
        for (int i = 0; i < 4; i++) {
            float m0 = -CUDART_INF_F, m1 = -CUDART_INF_F;
            #pragma unroll
            for (int jn = 0; jn < 4; jn++) {
                int nb = wn * 32 + jn * 8 + 2 * c;
                float bz0 = bias_s[nb], bz1 = bias_s[nb + 1];
                m0 = fmaxf(m0, fmaxf(d[i][jn][0] + bz0, d[i][jn][1] + bz1));
                m1 = fmaxf(m1, fmaxf(d[i][jn][2] + bz0, d[i][jn][3] + bz1));
            }
            m0 = fmaxf(m0, __shfl_xor_sync(0xffffffffu, m0, 1));
            m0 = fmaxf(m0, __shfl_xor_sync(0xffffffffu, m0, 2));
            m1 = fmaxf(m1, __shfl_xor_sync(0xffffffffu, m1, 1));
            m1 = fmaxf(m1, __shfl_xor_sync(0xffffffffu, m1, 2));
            if (c == 0) {
                redm[(wm * 64 + i * 16 + g) * 4 + wn]     = m0;
                redm[(wm * 64 + i * 16 + g + 8) * 4 + wn] = m1;
            }
        }
        if (fh) {
            float cs[4][2];
            #pragma unroll
            for (int jn = 0; jn < 4; jn++) { cs[jn][0] = 0.0f; cs[jn][1] = 0.0f; }
            #pragma unroll
            for (int i = 0; i < 4; i++) {
                float rf0 = rowfac_s[wm * 64 + i * 16 + g];
                float rf1 = rowfac_s[wm * 64 + i * 16 + g + 8];
                #pragma unroll
                for (int jn = 0; jn < 4; jn++) {
                    cs[jn][0] += d[i][jn][0] * rf0 + d[i][jn][2] * rf1;
                    cs[jn][1] += d[i][jn][1] * rf0 + d[i][jn][3] * rf1;
                }
            }
            #pragma unroll
            for (int jn = 0; jn < 4; jn++) {
                #pragma unroll
                for (int u = 0; u < 2; u++) {
                    float s = cs[jn][u];
                    s += __shfl_xor_sync(0xffffffffu, s, 4);
                    s += __shfl_xor_sync(0xffffffffu, s, 8);
                    s += __shfl_xor_sync(0xffffffffu, s, 16);
                    if (lane < 4) atomicAdd(&csum_s[wn * 32 + jn * 8 + 2 * c + u], s);
                }
            }
        }
        __syncthreads();
        if (tid < 128) {
            float m = fmaxf(fmaxf(redm[tid * 4 + 0], redm[tid * 4 + 1]),
                            fmaxf(redm[tid * 4 + 2], redm[tid * 4 + 3]));
            atomicMax(&g_rowmax[row0 + tid], enc_f(m));
        }
        if (fh && tid < 128) {
            int n = col0 + tid;
            if (n < NBLK) {
                int b = row0 >> 10;
                atomicAdd(&g_s[b * NBLK + n], csum_s[tid]);
            }
        }
    } else {
        float acc = 0.0f;
        #pragma unroll
        for (int i = 0; i < 4; i++) {
            int m0 = row0 + wm * 64 + i * 16 + g;
            #pragma unroll
            for (int jn = 0; jn < 4; jn++) {
                int n0 = col0 + wn * 32 + jn * 8 + 2 * c;
                float e;
                e = d[i][jn][0] - ((m0 == n0     && m0 < NBLK) ? 1.0f : 0.0f); acc += e * e;
                e = d[i][jn][1] - ((m0 == n0 + 1 && m0 < NBLK) ? 1.0f : 0.0f); acc += e * e;
                e = d[i][jn][2] - ((m0 + 8 == n0     && m0 + 8 < NBLK) ? 1.0f : 0.0f); acc += e * e;
                e = d[i][jn][3] - ((m0 + 8 == n0 + 1 && m0 + 8 < NBLK) ? 1.0f : 0.0f); acc += e * e;
            }
        }
        acc *= dupw;
        #pragma unroll
        for (int o = 16; o; o >>= 1) acc += __shfl_xor_sync(0xffffffffu, acc, o);
        if (lane == 0) csum_s[wid] = acc;
        __syncthreads();
        if (tid == 0) {
            float t = 0.0f;
            #pragma unroll
            for (int w = 0; w < 8; w++) t += csum_s[w];
            atomicAdd(&g_div, t);
        }
    }
}

// ---------------- finalize stage 1: 48 blocks ----------------
__global__ void finalize1_kernel(const int* __restrict__ mask) {
    __shared__ float red[32];
    int bidx = blockIdx.x, tid = threadIdx.x;
    int lane = tid & 31, wid = tid >> 5;
    if (bidx < 32) {
        int b = bidx;
        float mn = CUDART_INF_F;
        for (int t = tid; t < T_PER_B; t += blockDim.x) {
            int gr = b * T_PER_B + t;
            if (mask[gr] > 0) mn = fminf(mn, dec_f(g_rowmax[gr]));
        }
        #pragma unroll
        for (int o = 16; o; o >>= 1) mn = fminf(mn, __shfl_down_sync(0xffffffffu, mn, o));
        if (lane == 0) red[wid] = mn;
        __syncthreads();
        if (wid == 0) {
            float v = (lane < (int)(blockDim.x >> 5)) ? red[lane] : CUDART_INF_F;
            #pragma unroll
            for (int o = 16; o; o >>= 1) v = fminf(v, __shfl_down_sync(0xffffffffu, v, o));
            if (lane == 0) g_bmin[b] = v;
        }
    } else {
        int b = bidx - 32;
        float mx = -CUDART_INF_F;
        for (int n = tid; n < NBLK; n += blockDim.x) mx = fmaxf(mx, g_s[b * NBLK + n]);
        #pragma unroll
        for (int o = 16; o; o >>= 1) mx = fmaxf(mx, __shfl_down_sync(0xffffffffu, mx, o));
        if (lane == 0) red[wid] = mx;
        __syncthreads();
        if (wid == 0) {
            float v = (lane < (int)(blockDim.x >> 5)) ? red[lane] : -CUDART_INF_F;
            #pragma unroll
            for (int o = 16; o; o >>= 1) v = fmaxf(v, __shfl_down_sync(0xffffffffu, v, o));
            if (lane == 0) red[0] = v;
        }
        __syncthreads();
        mx = red[0];
        float se = 0.0f;
        for (int n = tid; n < NBLK; n += blockDim.x) se += expf(g_s[b * NBLK + n] - mx);
        #pragma unroll
        for (int o = 16; o; o >>= 1) se += __shfl_down_sync(0xffffffffu, se, o);
        __syncthreads();
        if (lane == 0) red[wid] = se;
        __syncthreads();
        if (wid == 0) {
            float v = (lane < (int)(blockDim.x >> 5)) ? red[lane] : 0.0f;
            #pragma unroll
            for (int o = 16; o; o >>= 1) v += __shfl_down_sync(0xffffffffu, v, o);
            if (lane == 0) { g_smaxv[b] = mx; g_sinvv[b] = 1.0f / v; }
        }
    }
}

// ---------------- finalize stage 2: 1 block ----------------
__global__ void finalize2_kernel(float* __restrict__ out) {
    __shared__ float red[32];
    __shared__ float smax[NB_HALF], sinv[NB_HALF];
    int tid = threadIdx.x, lane = tid & 31, wid = tid >> 5;
    if (tid < NB_HALF) { smax[tid] = g_smaxv[tid]; sinv[tid] = g_sinvv[tid]; }
    __syncthreads();

    float usq = 0.0f;
    for (int n = tid; n < NBLK; n += blockDim.x) {
        float tmp = 0.0f;
        #pragma unroll
        for (int b = 0; b < NB_HALF; b++)
            tmp += expf(g_s[b * NBLK + n] - smax[b]) * sinv[b];
        tmp *= (1.0f / (float)NB_HALF);
        usq += tmp * tmp;
    }
    #pragma unroll
    for (int o = 16; o; o >>= 1) usq += __shfl_down_sync(0xffffffffu, usq, o);
    if (lane == 0) red[wid] = usq;
    __syncthreads();
    if (wid == 0) {
        float v = (lane < (int)(blockDim.x >> 5)) ? red[lane] : 0.0f;
        #pragma unroll
        for (int o = 16; o; o >>= 1) v += __shfl_down_sync(0xffffffffu, v, o);
        if (lane == 0) {
            float mean_min = 0.0f, mean_ab = 0.0f;
            for (int b = 0; b < NB_HALF; b++) { mean_min += g_bmin[b]; mean_ab += g_bmin[NB_HALF + b]; }
            mean_min *= (1.0f / (float)NB_HALF);
            mean_ab  *= (1.0f / (float)NB_HALF);
            out[0] = 0.2f * sqrtf(g_div);
            out[1] = 2.0f - mean_min + mean_ab;
            out[2] = 0.5f * sqrtf(v);
        }
    }
}

// ---------------- launch ----------------
extern "C" void kernel_launch(void* const* d_in, const int* in_sizes, int n_in,
                              void* d_out, int out_size) {
    const float* x = nullptr;
    const int*   mask = nullptr;
    const float* w = nullptr;
    for (int i = 0; i < n_in; i++) {
        if (in_sizes[i] == NROWS * DIMK)      x = (const float*)d_in[i];
        else if (in_sizes[i] == NROWS)        mask = (const int*)d_in[i];
        else if (in_sizes[i] == NBLK * DIMK)  w = (const float*)d_in[i];
    }
    float* out = (float*)d_out;

    cudaFuncSetAttribute(gemm_run, cudaFuncAttributeMaxDynamicSharedMemorySize, SMEM_BYTES);

    conv_kernel<<<NROWS + NPAD, 256>>>(x, w);
    gemm_run<<<N_ATT_CTAS + N_DIV_CTAS, NTH, SMEM_BYTES>>>(mask);
    finalize1_kernel<<<48, 256>>>(mask);
    finalize2_kernel<<<1, 1024>>>(out);
}